// round 9
// baseline (speedup 1.0000x reference)
#include <cuda_runtime.h>
#include <cstdint>

#define BATCH 8
#define CDIM 64
#define NDIM 110592                 // 48*48*48
#define CN (CDIM*NDIM)

#define CHUNK 2048
#define NCHK (NDIM/CHUNK)           // 54
#define NIT (CHUNK/64)              // 32

#define TILE3 1024
#define SUB 64
#define NSUB (TILE3/SUB)            // 16
#define NTB3 (NDIM/TILE3)           // 108

#define NPROD 100
#define NCONS 196
#define TOTAL (NPROD+NCONS)         // 296 = 148*2 -> all resident at occ 2

// scratch (no cudaMalloc allowed)
__device__ float    g_partial[BATCH*NCHK][CDIM*CDIM];
__device__ uint32_t g_affp[BATCH][CDIM*32];          // packed bf16-pair affinity
__device__ int      g_cnt[BATCH];
__device__ int      g_flag[BATCH];

__device__ __forceinline__ uint32_t packbf(float lo, float hi) {
    uint32_t r;
    asm("cvt.rn.satfinite.bf16x2.f32 %0, %1, %2;" : "=r"(r) : "f"(hi), "f"(lo));
    return r;
}
__device__ __forceinline__ void mma_bf16(float* d, const uint32_t* a,
                                         uint32_t b0, uint32_t b1) {
    asm volatile("mma.sync.aligned.m16n8k16.row.col.f32.bf16.bf16.f32 "
                 "{%0,%1,%2,%3}, {%4,%5,%6,%7}, {%8,%9}, {%0,%1,%2,%3};"
                 : "+f"(d[0]), "+f"(d[1]), "+f"(d[2]), "+f"(d[3])
                 : "r"(a[0]), "r"(a[1]), "r"(a[2]), "r"(a[3]), "r"(b0), "r"(b1));
}
__device__ __forceinline__ void ldsm_x4(uint32_t* r, uint32_t addr) {
    asm volatile("ldmatrix.sync.aligned.m8n8.x4.shared.b16 {%0,%1,%2,%3}, [%4];"
                 : "=r"(r[0]), "=r"(r[1]), "=r"(r[2]), "=r"(r[3]) : "r"(addr));
}
__device__ __forceinline__ void ldsm_x4_t(uint32_t* r, uint32_t addr) {
    asm volatile("ldmatrix.sync.aligned.m8n8.x4.trans.shared.b16 {%0,%1,%2,%3}, [%4];"
                 : "=r"(r[0]), "=r"(r[1]), "=r"(r[2]), "=r"(r[3]) : "r"(addr));
}

// shared-memory overlays
struct GramSm  { uint32_t tile[2][CDIM][36]; };                    // 18432 B
struct AffSm   { float Gs[CDIM][CDIM + 1]; };                      // 16640 B
struct ApplySm { uint32_t Tl[2][CDIM][36]; float Os[CDIM][68]; };  // 35840 B

// ---------------------------------------------------------------------------
// gram chunk (proven R8 body): partial Gram of one 2048-wide chunk
// ---------------------------------------------------------------------------
__device__ void do_gram(const float* __restrict__ x, int b, int chunk, GramSm* S) {
    const float* xb = x + (size_t)b * CN + (size_t)chunk * CHUNK;
    int tid = threadIdx.x;
    int lane = tid & 31, warp = tid >> 5;
    int gid = lane >> 2, tg = lane & 3;
    int kg = warp >> 2;
    int m0 = ((warp >> 1) & 1) * 32;
    int n0 = (warp & 1) * 32;

    int r16 = tid >> 4, c16 = tid & 15;
    const float* rowp = xb + (size_t)r16 * NDIM + c16 * 4;

    int arow = (lane & 7) + ((lane >> 3) & 1) * 8;
    int acol = ((lane >> 4) & 1) * 4;
    int brow = (lane & 7) + ((lane >> 4) & 1) * 8;
    int bcol = ((lane >> 3) & 1) * 4;
    uint32_t base0 = (uint32_t)__cvta_generic_to_shared(&S->tile[0][0][0]);
    uint32_t base1 = (uint32_t)__cvta_generic_to_shared(&S->tile[1][0][0]);
    uint32_t offA0 = ((m0 + arow) * 36 + acol) * 4;
    uint32_t offA1 = ((m0 + 16 + arow) * 36 + acol) * 4;
    uint32_t offB0 = ((n0 + brow) * 36 + bcol) * 4;
    uint32_t offB1 = ((n0 + 16 + brow) * 36 + bcol) * 4;
    uint32_t kgoff = (uint32_t)(kg * 16 * 4);

    float acc[2][4][4];
#pragma unroll
    for (int mi = 0; mi < 2; mi++)
#pragma unroll
        for (int t = 0; t < 4; t++)
#pragma unroll
            for (int i = 0; i < 4; i++) acc[mi][t][i] = 0.f;

    float4 v[2][4];
#pragma unroll
    for (int j = 0; j < 4; j++) v[0][j] = *(const float4*)(rowp + (size_t)(16 * j) * NDIM);
#pragma unroll
    for (int j = 0; j < 4; j++) v[1][j] = *(const float4*)(rowp + (size_t)(16 * j) * NDIM + 64);
#pragma unroll
    for (int j = 0; j < 4; j++) {
        uint32_t p0 = packbf(v[0][j].x, v[0][j].y);
        uint32_t p1 = packbf(v[0][j].z, v[0][j].w);
        *(uint2*)&S->tile[0][r16 + 16 * j][2 * c16] = make_uint2(p0, p1);
    }
    __syncthreads();

    for (int it = 0; it < NIT; it++) {
        int p = it & 1;
        if (it + 2 < NIT) {
            const float* src = rowp + (it + 2) * 64;
#pragma unroll
            for (int j = 0; j < 4; j++) v[p][j] = *(const float4*)(src + (size_t)(16 * j) * NDIM);
        }
        uint32_t baseP = p ? base1 : base0;
#pragma unroll
        for (int s = 0; s < 2; s++) {
            uint32_t co = kgoff + s * 32;
            uint32_t a0[4], a1[4], bA[4], bB[4];
            ldsm_x4(a0, baseP + offA0 + co);
            ldsm_x4(a1, baseP + offA1 + co);
            ldsm_x4(bA, baseP + offB0 + co);
            ldsm_x4(bB, baseP + offB1 + co);
            mma_bf16(acc[0][0], a0, bA[0], bA[1]);
            mma_bf16(acc[0][1], a0, bA[2], bA[3]);
            mma_bf16(acc[0][2], a0, bB[0], bB[1]);
            mma_bf16(acc[0][3], a0, bB[2], bB[3]);
            mma_bf16(acc[1][0], a1, bA[0], bA[1]);
            mma_bf16(acc[1][1], a1, bA[2], bA[3]);
            mma_bf16(acc[1][2], a1, bB[0], bB[1]);
            mma_bf16(acc[1][3], a1, bB[2], bB[3]);
        }
        if (it + 1 < NIT) {
#pragma unroll
            for (int j = 0; j < 4; j++) {
                uint32_t p0 = packbf(v[p ^ 1][j].x, v[p ^ 1][j].y);
                uint32_t p1 = packbf(v[p ^ 1][j].z, v[p ^ 1][j].w);
                *(uint2*)&S->tile[p ^ 1][r16 + 16 * j][2 * c16] = make_uint2(p0, p1);
            }
        }
        __syncthreads();
    }

    float* red = (float*)&S->tile[0][0][0];
    if (kg == 1) {
        float* dst = red + ((warp & 3) * 32 + lane) * 32;
#pragma unroll
        for (int mi = 0; mi < 2; mi++)
#pragma unroll
            for (int t = 0; t < 4; t++)
#pragma unroll
                for (int i = 0; i < 4; i++) dst[mi * 16 + t * 4 + i] = acc[mi][t][i];
    }
    __syncthreads();
    if (kg == 0) {
        const float* src = red + ((warp & 3) * 32 + lane) * 32;
        float* gp = g_partial[b * NCHK + chunk];
#pragma unroll
        for (int mi = 0; mi < 2; mi++)
#pragma unroll
            for (int t = 0; t < 4; t++) {
                float a0 = acc[mi][t][0] + src[mi * 16 + t * 4 + 0];
                float a1 = acc[mi][t][1] + src[mi * 16 + t * 4 + 1];
                float a2 = acc[mi][t][2] + src[mi * 16 + t * 4 + 2];
                float a3 = acc[mi][t][3] + src[mi * 16 + t * 4 + 3];
                int r0 = m0 + 16 * mi + gid;
                int cc = n0 + 8 * t + 2 * tg;
                gp[r0 * CDIM + cc]           = a0;
                gp[r0 * CDIM + cc + 1]       = a1;
                gp[(r0 + 8) * CDIM + cc]     = a2;
                gp[(r0 + 8) * CDIM + cc + 1] = a3;
            }
    }
}

// ---------------------------------------------------------------------------
// affinity for one batch (proven body): reduce partials, G@G, sigmoid, pack
// ---------------------------------------------------------------------------
__device__ void do_affinity(int b, AffSm* S) {
    int tid = threadIdx.x;
    float s[16];
#pragma unroll
    for (int u = 0; u < 16; u++) s[u] = 0.f;
    for (int j = 0; j < NCHK; j++) {
        const float* gp = g_partial[b * NCHK + j];
#pragma unroll
        for (int u = 0; u < 16; u++) s[u] += gp[tid + 256 * u];
    }
#pragma unroll
    for (int u = 0; u < 16; u++) {
        int idx = tid + 256 * u;
        S->Gs[idx >> 6][idx & 63] = s[u];
    }
    __syncthreads();

    int r = tid >> 2;
    int c0 = (tid & 3) * 16;
    float vals[16];
#pragma unroll
    for (int j = 0; j < 16; j++) {
        float acc = 0.f;
#pragma unroll 8
        for (int d = 0; d < CDIM; d++)
            acc += S->Gs[r][d] * S->Gs[d][c0 + j];
        vals[j] = 1.f / (1.f + expf(-acc));
    }
    uint32_t pw[8];
#pragma unroll
    for (int j = 0; j < 8; j++) pw[j] = packbf(vals[2 * j], vals[2 * j + 1]);
    uint32_t* dst = &g_affp[b][r * 32 + (tid & 3) * 8];
    *(uint4*)(dst)     = make_uint4(pw[0], pw[1], pw[2], pw[3]);
    *(uint4*)(dst + 4) = make_uint4(pw[4], pw[5], pw[6], pw[7]);
}

// ---------------------------------------------------------------------------
// apply tile (proven R8 body): out = gamma*(Aff@K) + x for one 1024-col tile
// ---------------------------------------------------------------------------
__device__ void do_apply(const float* __restrict__ x, float gamma,
                         float* __restrict__ out, int b, int tblk, ApplySm* S) {
    size_t base = (size_t)b * CN;
    const float* xb = x + base + (size_t)tblk * TILE3;
    float* ob = out + base + (size_t)tblk * TILE3;

    int tid = threadIdx.x;
    int lane = tid & 31, warp = tid >> 5;
    int gid = lane >> 2, tg = lane & 3;
    int m0 = (warp & 1) * 32;
    int n0w = (warp >> 1) * 16;

    const uint32_t* PA = g_affp[b];
    uint32_t afr[2][4][4];
#pragma unroll
    for (int mi = 0; mi < 2; mi++) {
        int mr = m0 + 16 * mi + gid;
#pragma unroll
        for (int s = 0; s < 4; s++) {
            int pa = s * 8 + tg;
            afr[mi][s][0] = PA[mr * 32 + pa];
            afr[mi][s][1] = PA[(mr + 8) * 32 + pa];
            afr[mi][s][2] = PA[mr * 32 + pa + 4];
            afr[mi][s][3] = PA[(mr + 8) * 32 + pa + 4];
        }
    }

    int r16 = tid >> 4, c16 = tid & 15;
    const float* rowp = xb + (size_t)r16 * NDIM + c16 * 4;

    int brow2 = (lane & 7) + ((lane >> 3) & 1) * 8;
    int bnoff = ((lane >> 4) & 1) * 8;
    uint32_t tb0 = (uint32_t)__cvta_generic_to_shared(&S->Tl[0][0][0]);
    uint32_t tb1 = (uint32_t)__cvta_generic_to_shared(&S->Tl[1][0][0]);
    uint32_t offB = (uint32_t)(brow2 * 144 + (n0w + bnoff) * 2);

    float4 v[2][4];
#pragma unroll
    for (int j = 0; j < 4; j++) v[0][j] = *(const float4*)(rowp + (size_t)(16 * j) * NDIM);
#pragma unroll
    for (int j = 0; j < 4; j++) {
        uint32_t p0 = packbf(v[0][j].x, v[0][j].y);
        uint32_t p1 = packbf(v[0][j].z, v[0][j].w);
        *(uint2*)&S->Tl[0][r16 + 16 * j][2 * c16] = make_uint2(p0, p1);
    }
    __syncthreads();

    for (int sub = 0; sub < NSUB; sub++) {
        int q = sub & 1;
        int nbase = sub * SUB;

        if (sub + 1 < NSUB) {
            const float* src = rowp + (sub + 1) * SUB;
#pragma unroll
            for (int j = 0; j < 4; j++) v[q ^ 1][j] = *(const float4*)(src + (size_t)(16 * j) * NDIM);
        }

        float acc[2][2][4];
#pragma unroll
        for (int mi = 0; mi < 2; mi++)
#pragma unroll
            for (int t = 0; t < 2; t++)
#pragma unroll
                for (int i = 0; i < 4; i++) acc[mi][t][i] = 0.f;

        uint32_t baseQ = q ? tb1 : tb0;
#pragma unroll
        for (int s = 0; s < 4; s++) {
            uint32_t br[4];
            ldsm_x4_t(br, baseQ + offB + (uint32_t)(s * 16 * 144));
            mma_bf16(acc[0][0], afr[0][s], br[0], br[1]);
            mma_bf16(acc[1][0], afr[1][s], br[0], br[1]);
            mma_bf16(acc[0][1], afr[0][s], br[2], br[3]);
            mma_bf16(acc[1][1], afr[1][s], br[2], br[3]);
        }

#pragma unroll
        for (int mi = 0; mi < 2; mi++)
#pragma unroll
            for (int t = 0; t < 2; t++) {
                int cc = n0w + t * 8 + 2 * tg;
                int r0 = m0 + 16 * mi + gid;
                *(float2*)&S->Os[r0][cc]     = make_float2(acc[mi][t][0], acc[mi][t][1]);
                *(float2*)&S->Os[r0 + 8][cc] = make_float2(acc[mi][t][2], acc[mi][t][3]);
            }
        __syncthreads();

#pragma unroll
        for (int j = 0; j < 4; j++) {
            int r = r16 + 16 * j;
            float4 o = *(float4*)&S->Os[r][4 * c16];
            float4 xv = v[q][j];
            float4 res = make_float4(fmaf(gamma, o.x, xv.x), fmaf(gamma, o.y, xv.y),
                                     fmaf(gamma, o.z, xv.z), fmaf(gamma, o.w, xv.w));
            *(float4*)(ob + (size_t)r * NDIM + nbase + 4 * c16) = res;
        }

        if (sub + 1 < NSUB) {
#pragma unroll
            for (int j = 0; j < 4; j++) {
                uint32_t p0 = packbf(v[q ^ 1][j].x, v[q ^ 1][j].y);
                uint32_t p1 = packbf(v[q ^ 1][j].z, v[q ^ 1][j].w);
                *(uint2*)&S->Tl[q ^ 1][r16 + 16 * j][2 * c16] = make_uint2(p0, p1);
            }
        }
        __syncthreads();
    }
}

// ---------------------------------------------------------------------------
// prologue: reset handshake state each launch (graph-replay safe)
// ---------------------------------------------------------------------------
__global__ void init_kernel() {
    int t = threadIdx.x;
    if (t < BATCH) { g_cnt[t] = 0; g_flag[t] = 0; }
}

// ---------------------------------------------------------------------------
// fused persistent kernel: 100 producer blocks (gram+affinity) overlap
// 196 consumer blocks (apply) via per-batch release/acquire flags.
// Grid 296 = 148 SMs x occ 2 -> all blocks co-resident (no deadlock).
// ---------------------------------------------------------------------------
__global__ __launch_bounds__(256, 2) void fused_kernel(const float* __restrict__ x,
                                                       const float* __restrict__ gamma_p,
                                                       float* __restrict__ out) {
    __shared__ __align__(16) unsigned char smraw[sizeof(ApplySm)];
    __shared__ int sflag;
    int bid = blockIdx.x;

    if (bid < NPROD) {
        for (int w = bid; w < BATCH * NCHK; w += NPROD) {
            int b = w / NCHK, chunk = w % NCHK;
            do_gram(x, b, chunk, (GramSm*)smraw);
            __syncthreads();               // all partial writes issued
            __threadfence();               // release partials
            if (threadIdx.x == 0)
                sflag = (atomicAdd(&g_cnt[b], 1) == NCHK - 1);
            __syncthreads();
            if (sflag) {
                __threadfence();           // acquire all partials
                do_affinity(b, (AffSm*)smraw);
                __syncthreads();
                __threadfence();           // release g_affp
                if (threadIdx.x == 0) atomicExch(&g_flag[b], 1);
            }
            __syncthreads();               // smem reuse barrier
        }
    } else {
        float gamma = *gamma_p;
        int q = bid - NPROD;
        int lastb = -1;
        for (int t = q; t < BATCH * NTB3; t += NCONS) {
            int b = t / NTB3, tblk = t % NTB3;
            if (b != lastb) {
                if (threadIdx.x == 0) {
                    while (((volatile int*)g_flag)[b] == 0) __nanosleep(128);
                }
                __syncthreads();
                __threadfence();           // acquire g_affp
                lastb = b;
            }
            do_apply(x, gamma, out, b, tblk, (ApplySm*)smraw);
            __syncthreads();               // smem reuse barrier
        }
    }
}

extern "C" void kernel_launch(void* const* d_in, const int* in_sizes, int n_in,
                              void* d_out, int out_size) {
    (void)in_sizes; (void)n_in; (void)out_size;
    const float* x = (const float*)d_in[0];
    const float* gamma = (const float*)d_in[1];
    float* out = (float*)d_out;

    init_kernel<<<1, 32>>>();
    fused_kernel<<<TOTAL, 256>>>(x, gamma, out);
}

// round 11
// speedup vs baseline: 2.3582x; 2.3582x over previous
#include <cuda_runtime.h>
#include <cstdint>

#define BATCH 8
#define CDIM 64
#define NDIM 110592                 // 48*48*48
#define CN (CDIM*NDIM)

#define CHUNK 2048
#define NCHK (NDIM/CHUNK)           // 54
#define GBLOCKS (BATCH*NCHK)        // 432
#define NIT (CHUNK/64)              // 32

#define TILE3 1024
#define SUB 64
#define NSUB (TILE3/SUB)            // 16

// scratch (no cudaMalloc allowed)
__device__ float    g_partial[GBLOCKS][CDIM*CDIM];   // 7.08 MB
__device__ uint32_t g_affp[BATCH][CDIM*32];          // packed bf16-pair affinity [c][pd]

__device__ __forceinline__ uint32_t packbf(float lo, float hi) {
    uint32_t r;   // PTX operand order: d, a(hi), b(lo)
    asm("cvt.rn.satfinite.bf16x2.f32 %0, %1, %2;" : "=r"(r) : "f"(hi), "f"(lo));
    return r;
}

__device__ __forceinline__ void mma_bf16(float* d,
                                         uint32_t a0, uint32_t a1, uint32_t a2, uint32_t a3,
                                         uint32_t b0, uint32_t b1) {
    asm volatile("mma.sync.aligned.m16n8k16.row.col.f32.bf16.bf16.f32 "
                 "{%0,%1,%2,%3}, {%4,%5,%6,%7}, {%8,%9}, {%0,%1,%2,%3};"
                 : "+f"(d[0]), "+f"(d[1]), "+f"(d[2]), "+f"(d[3])
                 : "r"(a0), "r"(a1), "r"(a2), "r"(a3), "r"(b0), "r"(b1));
}

// ---------------------------------------------------------------------------
// Pass 1: partial Gram with bf16 m16n8k16 MMA, K=64 slabs, double-buffered.
// x loads use evict-first (__ldcs): gram's read never fits L2 anyway.
// ---------------------------------------------------------------------------
__global__ __launch_bounds__(256) void gram_kernel(const float* __restrict__ x) {
    int b = blockIdx.x / NCHK;
    int chunk = blockIdx.x % NCHK;
    const float* xb = x + (size_t)b * CN + (size_t)chunk * CHUNK;

    __shared__ uint32_t tile[2][CDIM][36];

    int tid = threadIdx.x;
    int lane = tid & 31, warp = tid >> 5;
    int gid = lane >> 2, tg = lane & 3;
    int m0 = (warp & 3) * 16;
    int n0 = (warp >> 2) * 32;

    int lrow = tid >> 2;
    int cb = (tid & 3) * 4;
    const float* rowp = xb + (size_t)lrow * NDIM + cb;
    int pbase = (tid & 3) * 2;

    float acc[4][4];
#pragma unroll
    for (int t = 0; t < 4; t++)
#pragma unroll
        for (int i = 0; i < 4; i++) acc[t][i] = 0.f;

    float4 v[4];
#pragma unroll
    for (int i = 0; i < 4; i++) v[i] = __ldcs((const float4*)(rowp + 16 * i));
#pragma unroll
    for (int i = 0; i < 4; i++) {
        uint32_t p0 = packbf(v[i].x, v[i].y);
        uint32_t p1 = packbf(v[i].z, v[i].w);
        *(uint2*)&tile[0][lrow][pbase + 8 * i] = make_uint2(p0, p1);
    }
    __syncthreads();

    for (int it = 0; it < NIT; it++) {
        if (it + 1 < NIT) {
            const float* src = rowp + (it + 1) * 64;
#pragma unroll
            for (int i = 0; i < 4; i++) v[i] = __ldcs((const float4*)(src + 16 * i));
        }
        {
            const uint32_t (*T)[36] = tile[it & 1];
#pragma unroll
            for (int s = 0; s < 4; s++) {
                int pa = 8 * s + tg;
                uint32_t a0 = T[m0 + gid][pa];
                uint32_t a1 = T[m0 + 8 + gid][pa];
                uint32_t a2 = T[m0 + gid][pa + 4];
                uint32_t a3 = T[m0 + 8 + gid][pa + 4];
#pragma unroll
                for (int t = 0; t < 4; t++) {
                    uint32_t b0 = T[n0 + t * 8 + gid][pa];
                    uint32_t b1 = T[n0 + t * 8 + gid][pa + 4];
                    mma_bf16(acc[t], a0, a1, a2, a3, b0, b1);
                }
            }
        }
        __syncthreads();
        if (it + 1 < NIT) {
            int bi = (it + 1) & 1;
#pragma unroll
            for (int i = 0; i < 4; i++) {
                uint32_t p0 = packbf(v[i].x, v[i].y);
                uint32_t p1 = packbf(v[i].z, v[i].w);
                *(uint2*)&tile[bi][lrow][pbase + 8 * i] = make_uint2(p0, p1);
            }
        }
        __syncthreads();
    }

    float* gp = g_partial[blockIdx.x];
#pragma unroll
    for (int t = 0; t < 4; t++) {
        int cc = n0 + t * 8 + tg * 2;
        gp[(m0 + gid) * CDIM + cc]         = acc[t][0];
        gp[(m0 + gid) * CDIM + cc + 1]     = acc[t][1];
        gp[(m0 + 8 + gid) * CDIM + cc]     = acc[t][2];
        gp[(m0 + 8 + gid) * CDIM + cc + 1] = acc[t][3];
    }
}

// ---------------------------------------------------------------------------
// Pass 2: reduce partials -> G, m3 = G@G, affinity = sigmoid(m3),
// emitted PRE-PACKED as bf16 pairs along d: g_affp[b][c][pd].
// ---------------------------------------------------------------------------
__global__ __launch_bounds__(256) void affinity_kernel() {
    int b = blockIdx.x;
    __shared__ float Gs[CDIM][CDIM + 1];
    int tid = threadIdx.x;

    float s[16];
#pragma unroll
    for (int u = 0; u < 16; u++) s[u] = 0.f;
    for (int j = 0; j < NCHK; j++) {
        const float* gp = g_partial[b * NCHK + j];
#pragma unroll
        for (int u = 0; u < 16; u++) s[u] += gp[tid + 256 * u];
    }
#pragma unroll
    for (int u = 0; u < 16; u++) {
        int idx = tid + 256 * u;
        Gs[idx >> 6][idx & 63] = s[u];
    }
    __syncthreads();

    int r = tid >> 2;
    int c0 = (tid & 3) * 16;
    float vals[16];
#pragma unroll
    for (int j = 0; j < 16; j++) {
        float acc = 0.f;
#pragma unroll 8
        for (int d = 0; d < CDIM; d++)
            acc += Gs[r][d] * Gs[d][c0 + j];
        vals[j] = 1.f / (1.f + expf(-acc));
    }
    uint32_t pw[8];
#pragma unroll
    for (int j = 0; j < 8; j++) pw[j] = packbf(vals[2 * j], vals[2 * j + 1]);
    uint32_t* dst = &g_affp[b][r * 32 + (tid & 3) * 8];
    *(uint4*)(dst)     = make_uint4(pw[0], pw[1], pw[2], pw[3]);
    *(uint4*)(dst + 4) = make_uint4(pw[4], pw[5], pw[6], pw[7]);
}

// ---------------------------------------------------------------------------
// Pass 3: out = gamma * (Aff @ K) + x.  bf16 m16n8k16, m32 x n16 per warp.
// Single barrier per sub-iteration (double-buffered P makes the pre-pack
// sync redundant). Output stores use __stcs (evict-first) so the x addend
// re-read stays L2-hot. Addend prefetched into regs before the MMA block.
// ---------------------------------------------------------------------------
__global__ __launch_bounds__(256) void apply_kernel(const float* __restrict__ x,
                                                    const float* __restrict__ gamma_p,
                                                    float* __restrict__ out) {
    int b = blockIdx.x / (NDIM / TILE3);
    int tblk = blockIdx.x % (NDIM / TILE3);
    size_t base = (size_t)b * CN;
    const float* xb = x + base + (size_t)tblk * TILE3;
    float* ob = out + base + (size_t)tblk * TILE3;
    float gamma = *gamma_p;

    __shared__ uint32_t P[2][32][72];   // bf16 pairs along channel d, 64 n-cols

    int tid = threadIdx.x;
    int lane = tid & 31, warp = tid >> 5;
    int gid = lane >> 2, tg = lane & 3;
    int m0 = (warp & 1) * 32;
    int n0w = (warp >> 1) * 16;

    // A fragments: 2 m-slabs x 4 k-slabs x 4 regs (L2-broadcast)
    const uint32_t* PA = g_affp[b];
    uint32_t afr[2][4][4];
#pragma unroll
    for (int mi = 0; mi < 2; mi++) {
        int mr = m0 + 16 * mi + gid;
#pragma unroll
        for (int s = 0; s < 4; s++) {
            int pa = s * 8 + tg;
            afr[mi][s][0] = PA[mr * 32 + pa];
            afr[mi][s][1] = PA[(mr + 8) * 32 + pa];
            afr[mi][s][2] = PA[mr * 32 + pa + 4];
            afr[mi][s][3] = PA[(mr + 8) * 32 + pa + 4];
        }
    }

    // loader role: pair-row pr (rows 2pr,2pr+1), 8 cols at cg*8
    int pr = tid >> 3;
    int cg = tid & 7;
    const float* row0 = xb + (size_t)(2 * pr) * NDIM + cg * 8;
    const float* row1 = row0 + NDIM;

    float4 u0, u1, w0, w1;
    u0 = *(const float4*)(row0);
    u1 = *(const float4*)(row0 + 4);
    w0 = *(const float4*)(row1);
    w1 = *(const float4*)(row1 + 4);
    {
        uint4 p0 = make_uint4(packbf(u0.x, w0.x), packbf(u0.y, w0.y),
                              packbf(u0.z, w0.z), packbf(u0.w, w0.w));
        uint4 p1 = make_uint4(packbf(u1.x, w1.x), packbf(u1.y, w1.y),
                              packbf(u1.z, w1.z), packbf(u1.w, w1.w));
        *(uint4*)&P[0][pr][cg * 8]     = p0;
        *(uint4*)&P[0][pr][cg * 8 + 4] = p1;
    }
    __syncthreads();

    for (int sub = 0; sub < NSUB; sub++) {
        int p = sub & 1;
        int nbase = sub * SUB;

        // (1) prefetch sub+1 x tile into loader regs
        if (sub + 1 < NSUB) {
            const float* s0 = row0 + (sub + 1) * SUB;
            const float* s1 = row1 + (sub + 1) * SUB;
            u0 = *(const float4*)(s0);
            u1 = *(const float4*)(s0 + 4);
            w0 = *(const float4*)(s1);
            w1 = *(const float4*)(s1 + 4);
        }

        // (2) prefetch this sub's f32 addend into regs (L2-hot re-read)
        float2 xadd[2][2][2];           // [mi][half][t]
#pragma unroll
        for (int mi = 0; mi < 2; mi++)
#pragma unroll
            for (int h = 0; h < 2; h++) {
                int r = m0 + 16 * mi + 8 * h + gid;
#pragma unroll
                for (int t = 0; t < 2; t++) {
                    int cc = nbase + n0w + t * 8 + tg * 2;
                    xadd[mi][h][t] = *(const float2*)(xb + (size_t)r * NDIM + cc);
                }
            }

        // (3) MMA on P[p]
        float acc[2][2][4];
#pragma unroll
        for (int mi = 0; mi < 2; mi++)
#pragma unroll
            for (int t = 0; t < 2; t++)
#pragma unroll
                for (int i = 0; i < 4; i++) acc[mi][t][i] = 0.f;

#pragma unroll
        for (int s = 0; s < 4; s++) {
            int pa = s * 8 + tg;
#pragma unroll
            for (int t = 0; t < 2; t++) {
                int n = n0w + t * 8 + gid;
                uint32_t b0 = P[p][pa][n];
                uint32_t b1 = P[p][pa + 4][n];
                mma_bf16(acc[0][t], afr[0][s][0], afr[0][s][1], afr[0][s][2], afr[0][s][3], b0, b1);
                mma_bf16(acc[1][t], afr[1][s][0], afr[1][s][1], afr[1][s][2], afr[1][s][3], b0, b1);
            }
        }

        // (4) epilogue: evict-first streaming stores (out never re-read)
#pragma unroll
        for (int mi = 0; mi < 2; mi++)
#pragma unroll
            for (int t = 0; t < 2; t++) {
                int cc = nbase + n0w + t * 8 + tg * 2;
                int r0 = m0 + 16 * mi + gid, r1 = r0 + 8;
                float2 o0 = make_float2(fmaf(gamma, acc[mi][t][0], xadd[mi][0][t].x),
                                        fmaf(gamma, acc[mi][t][1], xadd[mi][0][t].y));
                float2 o1 = make_float2(fmaf(gamma, acc[mi][t][2], xadd[mi][1][t].x),
                                        fmaf(gamma, acc[mi][t][3], xadd[mi][1][t].y));
                __stcs((float2*)(ob + (size_t)r0 * NDIM + cc), o0);
                __stcs((float2*)(ob + (size_t)r1 * NDIM + cc), o1);
            }

        // (5) pack sub+1 into P[p^1]; ONE barrier per iteration.
        // Safe: previous iter's reads of P[p^1] completed before the barrier
        // at the end of that iteration.
        if (sub + 1 < NSUB) {
            uint4 q0 = make_uint4(packbf(u0.x, w0.x), packbf(u0.y, w0.y),
                                  packbf(u0.z, w0.z), packbf(u0.w, w0.w));
            uint4 q1 = make_uint4(packbf(u1.x, w1.x), packbf(u1.y, w1.y),
                                  packbf(u1.z, w1.z), packbf(u1.w, w1.w));
            *(uint4*)&P[p ^ 1][pr][cg * 8]     = q0;
            *(uint4*)&P[p ^ 1][pr][cg * 8 + 4] = q1;
        }
        __syncthreads();
    }
}

extern "C" void kernel_launch(void* const* d_in, const int* in_sizes, int n_in,
                              void* d_out, int out_size) {
    (void)in_sizes; (void)n_in; (void)out_size;
    const float* x = (const float*)d_in[0];
    const float* gamma = (const float*)d_in[1];
    float* out = (float*)d_out;

    gram_kernel<<<GBLOCKS, 256>>>(x);
    affinity_kernel<<<BATCH, 256>>>();
    apply_kernel<<<BATCH * (NDIM / TILE3), 256>>>(x, gamma, out);
}

// round 13
// speedup vs baseline: 2.4070x; 1.0207x over previous
#include <cuda_runtime.h>
#include <cstdint>

#define BATCH 8
#define CDIM 64
#define NDIM 110592                 // 48*48*48
#define CN (CDIM*NDIM)

#define CHUNK 2048
#define NCHK (NDIM/CHUNK)           // 54
#define GBLOCKS (BATCH*NCHK)        // 432
#define NIT (CHUNK/64)              // 32

#define TILE3 1024
#define SUB 64
#define NSUB (TILE3/SUB)            // 16
#define NTB3 (NDIM/TILE3)           // 108

// scratch (no cudaMalloc allowed)
__device__ float    g_partial[GBLOCKS][CDIM*CDIM];   // 7.08 MB
__device__ uint32_t g_affp[BATCH][CDIM*32];          // packed bf16-pair affinity [c][pd]

__device__ __forceinline__ uint32_t packbf(float lo, float hi) {
    uint32_t r;   // PTX operand order: d, a(hi), b(lo)
    asm("cvt.rn.satfinite.bf16x2.f32 %0, %1, %2;" : "=r"(r) : "f"(hi), "f"(lo));
    return r;
}

__device__ __forceinline__ void mma_bf16(float* d,
                                         uint32_t a0, uint32_t a1, uint32_t a2, uint32_t a3,
                                         uint32_t b0, uint32_t b1) {
    asm volatile("mma.sync.aligned.m16n8k16.row.col.f32.bf16.bf16.f32 "
                 "{%0,%1,%2,%3}, {%4,%5,%6,%7}, {%8,%9}, {%0,%1,%2,%3};"
                 : "+f"(d[0]), "+f"(d[1]), "+f"(d[2]), "+f"(d[3])
                 : "r"(a0), "r"(a1), "r"(a2), "r"(a3), "r"(b0), "r"(b1));
}

// ---------------------------------------------------------------------------
// Pass 1: partial Gram with bf16 m16n8k16 MMA, K=64 slabs, double-buffered.
// Default cached loads: the tail of x stays L2-resident for apply.
// ---------------------------------------------------------------------------
__global__ __launch_bounds__(256) void gram_kernel(const float* __restrict__ x) {
    int b = blockIdx.x / NCHK;
    int chunk = blockIdx.x % NCHK;
    const float* xb = x + (size_t)b * CN + (size_t)chunk * CHUNK;

    __shared__ uint32_t tile[2][CDIM][36];

    int tid = threadIdx.x;
    int lane = tid & 31, warp = tid >> 5;
    int gid = lane >> 2, tg = lane & 3;
    int m0 = (warp & 3) * 16;
    int n0 = (warp >> 2) * 32;

    int lrow = tid >> 2;
    int cb = (tid & 3) * 4;
    const float* rowp = xb + (size_t)lrow * NDIM + cb;
    int pbase = (tid & 3) * 2;

    float acc[4][4];
#pragma unroll
    for (int t = 0; t < 4; t++)
#pragma unroll
        for (int i = 0; i < 4; i++) acc[t][i] = 0.f;

    float4 v[4];
#pragma unroll
    for (int i = 0; i < 4; i++) v[i] = *(const float4*)(rowp + 16 * i);
#pragma unroll
    for (int i = 0; i < 4; i++) {
        uint32_t p0 = packbf(v[i].x, v[i].y);
        uint32_t p1 = packbf(v[i].z, v[i].w);
        *(uint2*)&tile[0][lrow][pbase + 8 * i] = make_uint2(p0, p1);
    }
    __syncthreads();

    for (int it = 0; it < NIT; it++) {
        if (it + 1 < NIT) {
            const float* src = rowp + (it + 1) * 64;
#pragma unroll
            for (int i = 0; i < 4; i++) v[i] = *(const float4*)(src + 16 * i);
        }
        {
            const uint32_t (*T)[36] = tile[it & 1];
#pragma unroll
            for (int s = 0; s < 4; s++) {
                int pa = 8 * s + tg;
                uint32_t a0 = T[m0 + gid][pa];
                uint32_t a1 = T[m0 + 8 + gid][pa];
                uint32_t a2 = T[m0 + gid][pa + 4];
                uint32_t a3 = T[m0 + 8 + gid][pa + 4];
#pragma unroll
                for (int t = 0; t < 4; t++) {
                    uint32_t b0 = T[n0 + t * 8 + gid][pa];
                    uint32_t b1 = T[n0 + t * 8 + gid][pa + 4];
                    mma_bf16(acc[t], a0, a1, a2, a3, b0, b1);
                }
            }
        }
        __syncthreads();
        if (it + 1 < NIT) {
            int bi = (it + 1) & 1;
#pragma unroll
            for (int i = 0; i < 4; i++) {
                uint32_t p0 = packbf(v[i].x, v[i].y);
                uint32_t p1 = packbf(v[i].z, v[i].w);
                *(uint2*)&tile[bi][lrow][pbase + 8 * i] = make_uint2(p0, p1);
            }
        }
        __syncthreads();
    }

    float* gp = g_partial[blockIdx.x];
#pragma unroll
    for (int t = 0; t < 4; t++) {
        int cc = n0 + t * 8 + tg * 2;
        gp[(m0 + gid) * CDIM + cc]         = acc[t][0];
        gp[(m0 + gid) * CDIM + cc + 1]     = acc[t][1];
        gp[(m0 + 8 + gid) * CDIM + cc]     = acc[t][2];
        gp[(m0 + 8 + gid) * CDIM + cc + 1] = acc[t][3];
    }
}

// ---------------------------------------------------------------------------
// Pass 2: reduce partials -> G, m3 = G@G, affinity = sigmoid(m3),
// emitted PRE-PACKED as bf16 pairs along d: g_affp[b][c][pd].
// ---------------------------------------------------------------------------
__global__ __launch_bounds__(256) void affinity_kernel() {
    int b = blockIdx.x;
    __shared__ float Gs[CDIM][CDIM + 1];
    int tid = threadIdx.x;

    float s[16];
#pragma unroll
    for (int u = 0; u < 16; u++) s[u] = 0.f;
    for (int j = 0; j < NCHK; j++) {
        const float* gp = g_partial[b * NCHK + j];
#pragma unroll
        for (int u = 0; u < 16; u++) s[u] += gp[tid + 256 * u];
    }
#pragma unroll
    for (int u = 0; u < 16; u++) {
        int idx = tid + 256 * u;
        Gs[idx >> 6][idx & 63] = s[u];
    }
    __syncthreads();

    int r = tid >> 2;
    int c0 = (tid & 3) * 16;
    float vals[16];
#pragma unroll
    for (int j = 0; j < 16; j++) {
        float acc = 0.f;
#pragma unroll 8
        for (int d = 0; d < CDIM; d++)
            acc += Gs[r][d] * Gs[d][c0 + j];
        vals[j] = 1.f / (1.f + expf(-acc));
    }
    uint32_t pw[8];
#pragma unroll
    for (int j = 0; j < 8; j++) pw[j] = packbf(vals[2 * j], vals[2 * j + 1]);
    uint32_t* dst = &g_affp[b][r * 32 + (tid & 3) * 8];
    *(uint4*)(dst)     = make_uint4(pw[0], pw[1], pw[2], pw[3]);
    *(uint4*)(dst + 4) = make_uint4(pw[4], pw[5], pw[6], pw[7]);
}

// ---------------------------------------------------------------------------
// Pass 3: out = gamma * (Aff @ K) + x.  bf16 m16n8k16, m32 x n16 per warp.
// REVERSED tile traversal: first blocks read the x that gram touched last
// (L2-resident). Output stores evict-first (__stcs) to preserve x in L2.
// Structure otherwise identical to the 199.2us R6 version.
// ---------------------------------------------------------------------------
__global__ __launch_bounds__(256) void apply_kernel(const float* __restrict__ x,
                                                    const float* __restrict__ gamma_p,
                                                    float* __restrict__ out) {
    int gt = BATCH * NTB3 - 1 - blockIdx.x;   // reverse global tile order
    int b = gt / NTB3;
    int tblk = gt % NTB3;
    size_t base = (size_t)b * CN;
    const float* xb = x + base + (size_t)tblk * TILE3;
    float* ob = out + base + (size_t)tblk * TILE3;
    float gamma = *gamma_p;

    __shared__ uint32_t P[32][72];      // bf16 pairs along channel d, 64 n-cols

    int tid = threadIdx.x;
    int lane = tid & 31, warp = tid >> 5;
    int gid = lane >> 2, tg = lane & 3;
    int m0 = (warp & 1) * 32;
    int n0w = (warp >> 1) * 16;

    // A fragments: 2 m-slabs x 4 k-slabs x 4 regs (L2-broadcast)
    const uint32_t* PA = g_affp[b];
    uint32_t afr[2][4][4];
#pragma unroll
    for (int mi = 0; mi < 2; mi++) {
        int mr = m0 + 16 * mi + gid;
#pragma unroll
        for (int s = 0; s < 4; s++) {
            int pa = s * 8 + tg;
            afr[mi][s][0] = PA[mr * 32 + pa];
            afr[mi][s][1] = PA[(mr + 8) * 32 + pa];
            afr[mi][s][2] = PA[mr * 32 + pa + 4];
            afr[mi][s][3] = PA[(mr + 8) * 32 + pa + 4];
        }
    }

    // loader role: pair-row pr (rows 2pr,2pr+1), 8 cols at cg*8
    int pr = tid >> 3;
    int cg = tid & 7;
    const float* row0 = xb + (size_t)(2 * pr) * NDIM + cg * 8;
    const float* row1 = row0 + NDIM;

    float4 u0, u1, w0, w1;
    u0 = *(const float4*)(row0);
    u1 = *(const float4*)(row0 + 4);
    w0 = *(const float4*)(row1);
    w1 = *(const float4*)(row1 + 4);
    {
        uint4 p0 = make_uint4(packbf(u0.x, w0.x), packbf(u0.y, w0.y),
                              packbf(u0.z, w0.z), packbf(u0.w, w0.w));
        uint4 p1 = make_uint4(packbf(u1.x, w1.x), packbf(u1.y, w1.y),
                              packbf(u1.z, w1.z), packbf(u1.w, w1.w));
        *(uint4*)&P[pr][cg * 8]     = p0;
        *(uint4*)&P[pr][cg * 8 + 4] = p1;
    }
    __syncthreads();

    for (int sub = 0; sub < NSUB; sub++) {
        int nbase = sub * SUB;

        // (1) prefetch this sub's f32 addend into regs
        float2 xadd[2][2][2];           // [mi][half][t]
#pragma unroll
        for (int mi = 0; mi < 2; mi++)
#pragma unroll
            for (int h = 0; h < 2; h++) {
                int r = m0 + 16 * mi + 8 * h + gid;
#pragma unroll
                for (int t = 0; t < 2; t++) {
                    int cc = nbase + n0w + t * 8 + tg * 2;
                    xadd[mi][h][t] = *(const float2*)(xb + (size_t)r * NDIM + cc);
                }
            }

        // (2) prefetch next tile for the loader role
        if (sub + 1 < NSUB) {
            const float* s0 = row0 + (sub + 1) * SUB;
            const float* s1 = row1 + (sub + 1) * SUB;
            u0 = *(const float4*)(s0);
            u1 = *(const float4*)(s0 + 4);
            w0 = *(const float4*)(s1);
            w1 = *(const float4*)(s1 + 4);
        }

        // (3) MMA: 16 mmas; each B fragment pair shared by both m-slabs
        float acc[2][2][4];
#pragma unroll
        for (int mi = 0; mi < 2; mi++)
#pragma unroll
            for (int t = 0; t < 2; t++)
#pragma unroll
                for (int i = 0; i < 4; i++) acc[mi][t][i] = 0.f;

#pragma unroll
        for (int s = 0; s < 4; s++) {
            int pa = s * 8 + tg;
#pragma unroll
            for (int t = 0; t < 2; t++) {
                int n = n0w + t * 8 + gid;
                uint32_t b0 = P[pa][n];
                uint32_t b1 = P[pa + 4][n];
                mma_bf16(acc[0][t], afr[0][s][0], afr[0][s][1], afr[0][s][2], afr[0][s][3], b0, b1);
                mma_bf16(acc[1][t], afr[1][s][0], afr[1][s][1], afr[1][s][2], afr[1][s][3], b0, b1);
            }
        }

        // (4) epilogue: evict-first stores (out is dead data; keep x in L2)
#pragma unroll
        for (int mi = 0; mi < 2; mi++)
#pragma unroll
            for (int t = 0; t < 2; t++) {
                int cc = nbase + n0w + t * 8 + tg * 2;
                int r0 = m0 + 16 * mi + gid, r1 = r0 + 8;
                float2 o0 = make_float2(fmaf(gamma, acc[mi][t][0], xadd[mi][0][t].x),
                                        fmaf(gamma, acc[mi][t][1], xadd[mi][0][t].y));
                float2 o1 = make_float2(fmaf(gamma, acc[mi][t][2], xadd[mi][1][t].x),
                                        fmaf(gamma, acc[mi][t][3], xadd[mi][1][t].y));
                __stcs((float2*)(ob + (size_t)r0 * NDIM + cc), o0);
                __stcs((float2*)(ob + (size_t)r1 * NDIM + cc), o1);
            }

        if (sub + 1 < NSUB) {
            __syncthreads();        // all P reads done
            uint4 q0 = make_uint4(packbf(u0.x, w0.x), packbf(u0.y, w0.y),
                                  packbf(u0.z, w0.z), packbf(u0.w, w0.w));
            uint4 q1 = make_uint4(packbf(u1.x, w1.x), packbf(u1.y, w1.y),
                                  packbf(u1.z, w1.z), packbf(u1.w, w1.w));
            *(uint4*)&P[pr][cg * 8]     = q0;
            *(uint4*)&P[pr][cg * 8 + 4] = q1;
            __syncthreads();
        }
    }
}

extern "C" void kernel_launch(void* const* d_in, const int* in_sizes, int n_in,
                              void* d_out, int out_size) {
    (void)in_sizes; (void)n_in; (void)out_size;
    const float* x = (const float*)d_in[0];
    const float* gamma = (const float*)d_in[1];
    float* out = (float*)d_out;

    gram_kernel<<<GBLOCKS, 256>>>(x);
    affinity_kernel<<<BATCH, 256>>>();
    apply_kernel<<<BATCH * NTB3, 256>>>(x, gamma, out);
}

// round 15
// speedup vs baseline: 2.4233x; 1.0068x over previous
#include <cuda_runtime.h>
#include <cstdint>

#define BATCH 8
#define CDIM 64
#define NDIM 110592                 // 48*48*48
#define CN (CDIM*NDIM)

#define CHUNK 2048
#define NCHK (NDIM/CHUNK)           // 54
#define GBLOCKS (BATCH*NCHK)        // 432
#define NIT (CHUNK/64)              // 32

#define TILE3 1024
#define SUB 64
#define NSUB (TILE3/SUB)            // 16
#define NTB3 (NDIM/TILE3)           // 108

// scratch (no cudaMalloc allowed)
__device__ float    g_partial[GBLOCKS][CDIM*CDIM];   // 7.08 MB
__device__ uint32_t g_affp[BATCH][CDIM*32];          // packed bf16-pair affinity [c][pd]

__device__ __forceinline__ uint32_t packbf(float lo, float hi) {
    uint32_t r;   // PTX operand order: d, a(hi), b(lo)
    asm("cvt.rn.satfinite.bf16x2.f32 %0, %1, %2;" : "=r"(r) : "f"(hi), "f"(lo));
    return r;
}

__device__ __forceinline__ void mma_bf16(float* d,
                                         uint32_t a0, uint32_t a1, uint32_t a2, uint32_t a3,
                                         uint32_t b0, uint32_t b1) {
    asm volatile("mma.sync.aligned.m16n8k16.row.col.f32.bf16.bf16.f32 "
                 "{%0,%1,%2,%3}, {%4,%5,%6,%7}, {%8,%9}, {%0,%1,%2,%3};"
                 : "+f"(d[0]), "+f"(d[1]), "+f"(d[2]), "+f"(d[3])
                 : "r"(a0), "r"(a1), "r"(a2), "r"(a3), "r"(b0), "r"(b1));
}

// ---------------------------------------------------------------------------
// Pass 1: partial Gram with bf16 m16n8k16 MMA, K=64 slabs, double-buffered.
// (unchanged — 54us measured, protected)
// ---------------------------------------------------------------------------
__global__ __launch_bounds__(256) void gram_kernel(const float* __restrict__ x) {
    int b = blockIdx.x / NCHK;
    int chunk = blockIdx.x % NCHK;
    const float* xb = x + (size_t)b * CN + (size_t)chunk * CHUNK;

    __shared__ uint32_t tile[2][CDIM][36];

    int tid = threadIdx.x;
    int lane = tid & 31, warp = tid >> 5;
    int gid = lane >> 2, tg = lane & 3;
    int m0 = (warp & 3) * 16;
    int n0 = (warp >> 2) * 32;

    int lrow = tid >> 2;
    int cb = (tid & 3) * 4;
    const float* rowp = xb + (size_t)lrow * NDIM + cb;
    int pbase = (tid & 3) * 2;

    float acc[4][4];
#pragma unroll
    for (int t = 0; t < 4; t++)
#pragma unroll
        for (int i = 0; i < 4; i++) acc[t][i] = 0.f;

    float4 v[4];
#pragma unroll
    for (int i = 0; i < 4; i++) v[i] = *(const float4*)(rowp + 16 * i);
#pragma unroll
    for (int i = 0; i < 4; i++) {
        uint32_t p0 = packbf(v[i].x, v[i].y);
        uint32_t p1 = packbf(v[i].z, v[i].w);
        *(uint2*)&tile[0][lrow][pbase + 8 * i] = make_uint2(p0, p1);
    }
    __syncthreads();

    for (int it = 0; it < NIT; it++) {
        if (it + 1 < NIT) {
            const float* src = rowp + (it + 1) * 64;
#pragma unroll
            for (int i = 0; i < 4; i++) v[i] = *(const float4*)(src + 16 * i);
        }
        {
            const uint32_t (*T)[36] = tile[it & 1];
#pragma unroll
            for (int s = 0; s < 4; s++) {
                int pa = 8 * s + tg;
                uint32_t a0 = T[m0 + gid][pa];
                uint32_t a1 = T[m0 + 8 + gid][pa];
                uint32_t a2 = T[m0 + gid][pa + 4];
                uint32_t a3 = T[m0 + 8 + gid][pa + 4];
#pragma unroll
                for (int t = 0; t < 4; t++) {
                    uint32_t b0 = T[n0 + t * 8 + gid][pa];
                    uint32_t b1 = T[n0 + t * 8 + gid][pa + 4];
                    mma_bf16(acc[t], a0, a1, a2, a3, b0, b1);
                }
            }
        }
        __syncthreads();
        if (it + 1 < NIT) {
            int bi = (it + 1) & 1;
#pragma unroll
            for (int i = 0; i < 4; i++) {
                uint32_t p0 = packbf(v[i].x, v[i].y);
                uint32_t p1 = packbf(v[i].z, v[i].w);
                *(uint2*)&tile[bi][lrow][pbase + 8 * i] = make_uint2(p0, p1);
            }
        }
        __syncthreads();
    }

    float* gp = g_partial[blockIdx.x];
#pragma unroll
    for (int t = 0; t < 4; t++) {
        int cc = n0 + t * 8 + tg * 2;
        gp[(m0 + gid) * CDIM + cc]         = acc[t][0];
        gp[(m0 + gid) * CDIM + cc + 1]     = acc[t][1];
        gp[(m0 + 8 + gid) * CDIM + cc]     = acc[t][2];
        gp[(m0 + 8 + gid) * CDIM + cc + 1] = acc[t][3];
    }
}

// ---------------------------------------------------------------------------
// Pass 2: reduce partials -> G, m3 = G@G, affinity = sigmoid(m3),
// emitted PRE-PACKED as bf16 pairs along d: g_affp[b][c][pd].
// ---------------------------------------------------------------------------
__global__ __launch_bounds__(256) void affinity_kernel() {
    int b = blockIdx.x;
    __shared__ float Gs[CDIM][CDIM + 1];
    int tid = threadIdx.x;

    float s[16];
#pragma unroll
    for (int u = 0; u < 16; u++) s[u] = 0.f;
    for (int j = 0; j < NCHK; j++) {
        const float* gp = g_partial[b * NCHK + j];
#pragma unroll
        for (int u = 0; u < 16; u++) s[u] += gp[tid + 256 * u];
    }
#pragma unroll
    for (int u = 0; u < 16; u++) {
        int idx = tid + 256 * u;
        Gs[idx >> 6][idx & 63] = s[u];
    }
    __syncthreads();

    int r = tid >> 2;
    int c0 = (tid & 3) * 16;
    float vals[16];
#pragma unroll
    for (int j = 0; j < 16; j++) {
        float acc = 0.f;
#pragma unroll 8
        for (int d = 0; d < CDIM; d++)
            acc += Gs[r][d] * Gs[d][c0 + j];
        vals[j] = 1.f / (1.f + expf(-acc));
    }
    uint32_t pw[8];
#pragma unroll
    for (int j = 0; j < 8; j++) pw[j] = packbf(vals[2 * j], vals[2 * j + 1]);
    uint32_t* dst = &g_affp[b][r * 32 + (tid & 3) * 8];
    *(uint4*)(dst)     = make_uint4(pw[0], pw[1], pw[2], pw[3]);
    *(uint4*)(dst + 4) = make_uint4(pw[4], pw[5], pw[6], pw[7]);
}

// ---------------------------------------------------------------------------
// Pass 3: out = gamma * (Aff @ K) + x.  bf16 m16n8k16, m16 x n32 per warp.
// LOW-REGISTER variant pinned to 3 blocks/SM (__launch_bounds__(256,3)):
// afr is 16 regs (one m-slab), addend loaded directly in the epilogue
// (L1-hot — same tile the loader just fetched). Loader prefetch kept for MLP.
// ---------------------------------------------------------------------------
__global__ __launch_bounds__(256, 3) void apply_kernel(const float* __restrict__ x,
                                                       const float* __restrict__ gamma_p,
                                                       float* __restrict__ out) {
    int b = blockIdx.x / NTB3;
    int tblk = blockIdx.x % NTB3;
    size_t base = (size_t)b * CN;
    const float* xb = x + base + (size_t)tblk * TILE3;
    float* ob = out + base + (size_t)tblk * TILE3;
    float gamma = *gamma_p;

    __shared__ uint32_t P[32][72];      // bf16 pairs along channel d, 64 n-cols

    int tid = threadIdx.x;
    int lane = tid & 31, warp = tid >> 5;
    int gid = lane >> 2, tg = lane & 3;
    int m0 = (warp & 3) * 16;           // warp's 16-channel slab
    int n0w = (warp >> 2) * 32;         // warp's 32-col slice

    // A fragments: 4 k-slabs x 4 regs = 16 regs (L2-broadcast loads)
    const uint32_t* PA = g_affp[b];
    uint32_t afr[4][4];
#pragma unroll
    for (int s = 0; s < 4; s++) {
        int pa = s * 8 + tg;
        afr[s][0] = PA[(m0 + gid) * 32 + pa];
        afr[s][1] = PA[(m0 + 8 + gid) * 32 + pa];
        afr[s][2] = PA[(m0 + gid) * 32 + pa + 4];
        afr[s][3] = PA[(m0 + 8 + gid) * 32 + pa + 4];
    }

    // loader role: pair-row pr (rows 2pr,2pr+1), 8 cols at cg*8
    int pr = tid >> 3;
    int cg = tid & 7;
    const float* row0 = xb + (size_t)(2 * pr) * NDIM + cg * 8;
    const float* row1 = row0 + NDIM;

    float4 u0, u1, w0, w1;
    u0 = *(const float4*)(row0);
    u1 = *(const float4*)(row0 + 4);
    w0 = *(const float4*)(row1);
    w1 = *(const float4*)(row1 + 4);
    {
        uint4 p0 = make_uint4(packbf(u0.x, w0.x), packbf(u0.y, w0.y),
                              packbf(u0.z, w0.z), packbf(u0.w, w0.w));
        uint4 p1 = make_uint4(packbf(u1.x, w1.x), packbf(u1.y, w1.y),
                              packbf(u1.z, w1.z), packbf(u1.w, w1.w));
        *(uint4*)&P[pr][cg * 8]     = p0;
        *(uint4*)&P[pr][cg * 8 + 4] = p1;
    }
    __syncthreads();

    for (int sub = 0; sub < NSUB; sub++) {
        int nbase = sub * SUB;

        // (1) prefetch next tile for the loader role (keeps MLP up)
        if (sub + 1 < NSUB) {
            const float* s0 = row0 + (sub + 1) * SUB;
            const float* s1 = row1 + (sub + 1) * SUB;
            u0 = *(const float4*)(s0);
            u1 = *(const float4*)(s0 + 4);
            w0 = *(const float4*)(s1);
            w1 = *(const float4*)(s1 + 4);
        }

        // (2) MMA: m16 x n32 per warp, 16 mmas
        float acc[4][4];
#pragma unroll
        for (int t = 0; t < 4; t++)
#pragma unroll
            for (int i = 0; i < 4; i++) acc[t][i] = 0.f;

#pragma unroll
        for (int s = 0; s < 4; s++) {
            int pa = s * 8 + tg;
#pragma unroll
            for (int t = 0; t < 4; t++) {
                int n = n0w + t * 8 + gid;
                uint32_t b0 = P[pa][n];
                uint32_t b1 = P[pa + 4][n];
                mma_bf16(acc[t], afr[s][0], afr[s][1], afr[s][2], afr[s][3], b0, b1);
            }
        }

        // (3) epilogue: addend loaded directly (L1-hot), then store
#pragma unroll
        for (int t = 0; t < 4; t++) {
            int cc = nbase + n0w + t * 8 + tg * 2;
            int r0 = m0 + gid, r1 = r0 + 8;
            float2 x0 = *(const float2*)(xb + (size_t)r0 * NDIM + cc);
            float2 x1 = *(const float2*)(xb + (size_t)r1 * NDIM + cc);
            float2 o0 = make_float2(fmaf(gamma, acc[t][0], x0.x),
                                    fmaf(gamma, acc[t][1], x0.y));
            float2 o1 = make_float2(fmaf(gamma, acc[t][2], x1.x),
                                    fmaf(gamma, acc[t][3], x1.y));
            *(float2*)(ob + (size_t)r0 * NDIM + cc) = o0;
            *(float2*)(ob + (size_t)r1 * NDIM + cc) = o1;
        }

        if (sub + 1 < NSUB) {
            __syncthreads();        // all P reads done
            uint4 q0 = make_uint4(packbf(u0.x, w0.x), packbf(u0.y, w0.y),
                                  packbf(u0.z, w0.z), packbf(u0.w, w0.w));
            uint4 q1 = make_uint4(packbf(u1.x, w1.x), packbf(u1.y, w1.y),
                                  packbf(u1.z, w1.z), packbf(u1.w, w1.w));
            *(uint4*)&P[pr][cg * 8]     = q0;
            *(uint4*)&P[pr][cg * 8 + 4] = q1;
            __syncthreads();
        }
    }
}

extern "C" void kernel_launch(void* const* d_in, const int* in_sizes, int n_in,
                              void* d_out, int out_size) {
    (void)in_sizes; (void)n_in; (void)out_size;
    const float* x = (const float*)d_in[0];
    const float* gamma = (const float*)d_in[1];
    float* out = (float*)d_out;

    gram_kernel<<<GBLOCKS, 256>>>(x);
    affinity_kernel<<<BATCH, 256>>>();
    apply_kernel<<<BATCH * NTB3, 256>>>(x, gamma, out);
}